// round 1
// baseline (speedup 1.0000x reference)
#include <cuda_runtime.h>
#include <cuda_bf16.h>

// Problem shapes (fixed by the reference setup_inputs)
constexpr int B  = 2;
constexpr int CF = 64;    // feature channels
constexpr int H  = 64;
constexpr int W  = 2048;
constexpr int CC = 3;     // coord channels
constexpr int C0 = 16;    // w0 out
constexpr int C1 = 64;    // w1 out (== CF)

__global__ __launch_bounds__(256) void meta_fused_kernel(
    const float* __restrict__ features,   // [B, CF, H, W]
    const float* __restrict__ coord,      // [B, CC, H, W]
    const float* __restrict__ w0,         // [C0, CC]
    const float* __restrict__ w1,         // [C1, C0]
    float* __restrict__ out)              // [B, CF*9, H, W]
{
    // Fold the two linear layers (no nonlinearity between them):
    // Wc = w1 @ w0, shape [C1, CC]. Computed per block (cheap, L2-cached reads).
    __shared__ float sW[C1 * CC];
    const int t = threadIdx.x;
    if (t < C1 * CC) {
        const int o = t / CC, c = t % CC;
        float s = 0.f;
        #pragma unroll
        for (int k = 0; k < C0; k++)
            s = fmaf(w1[o * C0 + k], w0[k * CC + c], s);
        sW[t] = s;
    }
    __syncthreads();

    const int w = blockIdx.x * blockDim.x + t;
    const int h = blockIdx.y;
    const int b = blockIdx.z;

    // Neighborhood validity (zero padding in reference)
    bool hv0 = (h > 0), hv2 = (h < H - 1);
    bool wv0 = (w > 0), wv2 = (w < W - 1);
    bool valid[9];
    valid[0] = hv0 && wv0; valid[1] = hv0;        valid[2] = hv0 && wv2;
    valid[3] = wv0;        valid[4] = true;       valid[5] = wv2;
    valid[6] = hv2 && wv0; valid[7] = hv2;        valid[8] = hv2 && wv2;

    // Build rel[c][n] = coord_sample - center, masked where center == -1
    float rel[CC][9];
    #pragma unroll
    for (int c = 0; c < CC; c++) {
        const float* cb = coord + ((size_t)(b * CC + c) * H) * W;
        const float ctr = cb[h * W + w];
        const bool dead = (ctr == -1.0f);
        #pragma unroll
        for (int n = 0; n < 9; n++) {
            const int di = n / 3 - 1, dj = n % 3 - 1;
            float v = 0.f;
            if (valid[n]) v = cb[(h + di) * W + (w + dj)];
            rel[c][n] = dead ? 0.f : (v - ctr);
        }
    }

    const size_t hw   = (size_t)h * W + w;
    const size_t chan = (size_t)H * W;
    const float* fb = features + (size_t)b * CF * chan;
    float*       ob = out + (size_t)b * CF * 9 * chan + hw;

    #pragma unroll 2
    for (int cf = 0; cf < CF; cf++) {
        const float a0 = sW[cf * 3 + 0];
        const float a1 = sW[cf * 3 + 1];
        const float a2 = sW[cf * 3 + 2];
        const float* fc = fb + (size_t)cf * chan + hw;
        float*       oc = ob + (size_t)cf * 9 * chan;
        #pragma unroll
        for (int n = 0; n < 9; n++) {
            const int di = n / 3 - 1, dj = n % 3 - 1;
            float f = 0.f;
            if (valid[n]) f = fc[(size_t)di * W + dj];
            float wt = fmaf(a0, rel[0][n], fmaf(a1, rel[1][n], a2 * rel[2][n]));
            wt = fmaxf(wt, 0.f);
            oc[(size_t)n * chan] = f * wt;
        }
    }
}

extern "C" void kernel_launch(void* const* d_in, const int* in_sizes, int n_in,
                              void* d_out, int out_size) {
    const float* features = (const float*)d_in[0];
    const float* coord    = (const float*)d_in[1];
    const float* w0       = (const float*)d_in[2];
    const float* w1       = (const float*)d_in[3];
    float* out = (float*)d_out;

    dim3 grid(W / 256, H, B);
    meta_fused_kernel<<<grid, 256>>>(features, coord, w0, w1, out);
}